// round 14
// baseline (speedup 1.0000x reference)
#include <cuda_runtime.h>

// Multi-scale SSIM quadtree loss, N=256, levels d=8..0.
// Level d: block side h=256>>d, mu = block_sum/h (faithful reference bug),
// weight W[d] = K_LOSS[d]*0.25^d, K_LOSS={9,8,7,6,5,4,3,2,1}.
//
// TERMINAL KERNEL (validated 3x: wall 6.66/6.94/6.66us, ncu 6.18/6.62/6.24us).
// 256 CTAs x 128 threads; warp = 8x8 pixel block, lane = 1x2 strip;
// warp-shuffle quadtrees with weight/replication (exact pow2).
// Key win of the session: NO standalone threadfences — cross-CTA ordering
// lives entirely on one acq_rel ticket RMW (release orders the tile-record
// store; acquire orders the last CTA's reads). Flat ticket: hierarchical /
// hash-spread variants measured slower (the drain overlaps CTA arrival
// spread; only the last RMW is exposed). Grid-shape sweep 16..256 CTAs:
// neutral post-fence; launch cost is per-grid fixed.

#define SSIM_C1 0.2f

__device__ float4 g_tile[256];        // (Sx, Sy, partial, 0) per 16x16 tile
__device__ unsigned int g_count = 0;

// Weights pre-divided by lane replication (all exact in fp32):
#define W8_R 1.52587890625e-05f   // 1/65536          d=8 rep1
#define W7_R 6.103515625e-05f     // (2/16384)/2      d=7 rep2
#define W6_R 9.1552734375e-05f    // (3/4096)/8       d=6 rep8
#define W5_R 1.220703125e-04f     // (4/1024)/32      d=5 rep32
#define W4_F 0.01953125f          // 5/256            d=4 once
#define W3_R 0.046875f            // (6/64)/2         d=3 rep2
#define W2_R 0.0546875f           // (7/16)/8         d=2 rep8
#define W1_R 0.0625f              // (8/4)/32         d=1 rep32
#define W0_F 9.0f                 // 9                d=0 once

__device__ __forceinline__ float loss_term(float sx, float sy, float invh) {
    float mx = sx * invh;
    float my = sy * invh;
    return 1.0f - (2.0f * mx * my + SSIM_C1) / (mx * mx + my * my + SSIM_C1);
}

// Quadtree over an 8x8 grid of per-lane 1x2 sums (lane l -> row l>>2,
// colpair l&3). Adds 3 level terms, returns full 8x8-grid sums.
__device__ __forceinline__ void warp_quadtree(
    float s1x, float s1y, float& acc, float& s8x, float& s8y,
    float wA, float ihA, float wB, float ihB, float wC, float ihC)
{
    float s2x = s1x + __shfl_xor_sync(0xffffffffu, s1x, 4);
    float s2y = s1y + __shfl_xor_sync(0xffffffffu, s1y, 4);
    acc += wA * loss_term(s2x, s2y, ihA);
    float s4x = s2x + __shfl_xor_sync(0xffffffffu, s2x, 8);
    float s4y = s2y + __shfl_xor_sync(0xffffffffu, s2y, 8);
    s4x += __shfl_xor_sync(0xffffffffu, s4x, 1);
    s4y += __shfl_xor_sync(0xffffffffu, s4y, 1);
    acc += wB * loss_term(s4x, s4y, ihB);
    s8x = s4x + __shfl_xor_sync(0xffffffffu, s4x, 16);
    s8y = s4y + __shfl_xor_sync(0xffffffffu, s4y, 16);
    s8x += __shfl_xor_sync(0xffffffffu, s8x, 2);
    s8y += __shfl_xor_sync(0xffffffffu, s8y, 2);
    acc += wC * loss_term(s8x, s8y, ihC);
}

__device__ __forceinline__ float warp_sum(float v) {
    v += __shfl_xor_sync(0xffffffffu, v, 16);
    v += __shfl_xor_sync(0xffffffffu, v, 8);
    v += __shfl_xor_sync(0xffffffffu, v, 4);
    v += __shfl_xor_sync(0xffffffffu, v, 2);
    v += __shfl_xor_sync(0xffffffffu, v, 1);
    return v;
}

__global__ void __launch_bounds__(128) Loss_13967233646850_kernel(
    const float* __restrict__ x, const float* __restrict__ y,
    float* __restrict__ out)
{
    __shared__ float sSx[4], sSy[4], sAcc[4];
    __shared__ bool  isLast;

    const int tid  = threadIdx.x;
    const int lane = tid & 31;
    const int w    = tid >> 5;           // warp 0..3 -> quadrant of 16x16 tile
    const int b    = blockIdx.x;

    // ---- Phase A: d=8..5 over this warp's 8x8 pixel block ----
    {
        const int row = (b >> 4) * 16 + (w >> 1) * 8 + (lane >> 2);
        const int col = (b & 15) * 16 + (w & 1) * 8 + (lane & 3) * 2;
        const int idx = row * 256 + col;

        const float2 px = *(const float2*)(x + idx);
        const float2 py = *(const float2*)(y + idx);

        float acc = W8_R * (loss_term(px.x, py.x, 1.0f) +
                            loss_term(px.y, py.y, 1.0f));
        float s8x, s8y;
        warp_quadtree(px.x + px.y, py.x + py.y, acc, s8x, s8y,
                      W7_R, 0.5f, W6_R, 0.25f, W5_R, 0.125f);
        acc = warp_sum(acc);
        if (lane == 0) { sSx[w] = s8x; sSy[w] = s8y; sAcc[w] = acc; }
    }

    // Producers signal barrier 1; warp 0 waits on it then takes the ticket.
    if (w != 0) {
        asm volatile("bar.arrive 1, 128;" ::: "memory");
    } else {
        asm volatile("bar.sync 1, 128;" ::: "memory");
        // ---- Warp 0 lane 0: d=4 term, tile record, acq_rel ticket ----
        if (lane == 0) {
            float Sx = sSx[0] + sSx[1] + sSx[2] + sSx[3];
            float Sy = sSy[0] + sSy[1] + sSy[2] + sSy[3];
            float a  = sAcc[0] + sAcc[1] + sAcc[2] + sAcc[3];
            a += W4_F * loss_term(Sx, Sy, 1.0f / 16.0f);   // d=4 (16x16 tile)
            g_tile[b] = make_float4(Sx, Sy, a, 0.0f);
            // Single acq_rel RMW: release orders the record store above,
            // acquire orders the last CTA's g_tile reads below.
            unsigned int t;
            asm volatile("atom.add.acq_rel.gpu.global.u32 %0, [%1], 1;"
                         : "=r"(t) : "l"(&g_count) : "memory");
            isLast = (t == 255u);
        }
    }
    __syncthreads();
    if (!isLast) return;

    // ---- Phase B: last CTA, 16x16 tile grid, d=3..0 ----
    {
        // Warp w owns an 8x8 quadrant of the tile grid; lane = 1x2 tile pair.
        const int trow = (w >> 1) * 8 + (lane >> 2);
        const int tcol = (w & 1) * 8 + (lane & 3) * 2;
        const int ti   = trow * 16 + tcol;

        const float4 t0 = g_tile[ti];
        const float4 t1 = g_tile[ti + 1];

        float acc = t0.z + t1.z;
        float s8x, s8y;
        warp_quadtree(t0.x + t1.x, t0.y + t1.y, acc, s8x, s8y,
                      W3_R, 1.0f / 32.0f, W2_R, 1.0f / 64.0f, W1_R, 1.0f / 128.0f);
        acc = warp_sum(acc);
        if (lane == 0) { sSx[w] = s8x; sSy[w] = s8y; sAcc[w] = acc; }
    }
    __syncthreads();

    if (tid == 0) {
        float Sx = sSx[0] + sSx[1] + sSx[2] + sSx[3];
        float Sy = sSy[0] + sSy[1] + sSy[2] + sSy[3];
        float a  = sAcc[0] + sAcc[1] + sAcc[2] + sAcc[3];
        a += W0_F * loss_term(Sx, Sy, 1.0f / 256.0f);   // d=0 (full image)
        out[0] = a;
        g_count = 0;                                    // reset for graph replay
    }
}

extern "C" void kernel_launch(void* const* d_in, const int* in_sizes, int n_in,
                              void* d_out, int out_size) {
    const float* x = (const float*)d_in[0];
    const float* y = (const float*)d_in[1];
    float* out = (float*)d_out;
    Loss_13967233646850_kernel<<<256, 128>>>(x, y, out);
}